// round 1
// baseline (speedup 1.0000x reference)
#include <cuda_runtime.h>
#include <math.h>
#include <stdint.h>

// Problem constants
#define Nn 50000
#define Ee 400000
#define Pp 3
#define Hh 4
#define Dd 32
#define HDd 128

// ---------------- scratch (device globals; no allocations allowed) -------------
__device__ __align__(16) float    g_x[(size_t)Nn * 128];            // 25.6 MB
__device__ __align__(16) float    g_feat[(size_t)Pp * Nn * 128];    // 76.8 MB
__device__ __align__(16) float    g_z[(size_t)Pp * Nn * 128];       // 76.8 MB
__device__ __align__(16) float    g_el[(size_t)Pp * Nn * 4];
__device__ __align__(16) float    g_er[(size_t)Pp * Nn * 4];
__device__ __align__(16) float    g_ee[(size_t)Pp * Ee * 4];        // 19.2 MB
__device__ __align__(16) unsigned g_m[(size_t)Pp * Nn * 4];
__device__ __align__(16) float    g_zsum[(size_t)Pp * Nn * 4];
__device__ float g_wsem[Pp];
__device__ float g_bsem[Pp];

// order-preserving float<->uint encoding for atomicMax on floats
__device__ __forceinline__ unsigned encf(float f) {
    unsigned u = __float_as_uint(f);
    return (u & 0x80000000u) ? ~u : (u | 0x80000000u);
}
__device__ __forceinline__ float decf(unsigned u) {
    return __uint_as_float((u & 0x80000000u) ? (u & 0x7FFFFFFFu) : ~u);
}
#define ENC_NEG_INF 0x007FFFFFu   // encf(-inf)

// ---------------- init: m = enc(-inf), zsum = 0, wsem = 0 ----------------------
__global__ void k_init(unsigned* __restrict__ m, float* __restrict__ zsum,
                       float* __restrict__ wsem) {
    int i = blockIdx.x * 256 + threadIdx.x;
    if (i < Pp * Nn * 4) { m[i] = ENC_NEG_INF; zsum[i] = 0.f; }
    if (i < Pp) wsem[i] = 0.f;
}

// ---------------- feature attention: warp per node -----------------------------
// x[n, 0:86] = h[n]; x[n, 86:128] = sum_j softmax_j(tanh(f_j @ w1 + b1) @ w2) * f_j
__global__ void k_featatt(const float* __restrict__ h, const float* __restrict__ cf,
                          const float* __restrict__ w1, const float* __restrict__ b1,
                          const float* __restrict__ w2, float* __restrict__ x) {
    __shared__ float sw1[42 * 16];
    __shared__ float sb1[16], sw2[16];
    __shared__ float sf[8][840];
    __shared__ float ss[8][20];
    int tid = threadIdx.x, wid = tid >> 5, lane = tid & 31;
    for (int i = tid; i < 672; i += 256) sw1[i] = w1[i];
    if (tid < 16) { sb1[tid] = b1[tid]; sw2[tid] = w2[tid]; }
    __syncthreads();
    int n = blockIdx.x * 8 + wid;
    if (n >= Nn) return;

    const float* fr = cf + (size_t)n * 840;
    float* myf = sf[wid];
    for (int i = lane; i < 840; i += 32) myf[i] = fr[i];
    __syncwarp();

    int k = lane & 15;
    for (int j0 = 0; j0 < 20; j0 += 2) {
        int j = j0 + (lane >> 4);            // two neighbors per warp pass
        const float* fj = myf + j * 42;
        float acc = sb1[k];
#pragma unroll
        for (int i = 0; i < 42; i++) acc = fmaf(fj[i], sw1[i * 16 + k], acc);
        float v = tanhf(acc) * sw2[k];
#pragma unroll
        for (int off = 8; off; off >>= 1) v += __shfl_down_sync(0xffffffffu, v, off);
        if (k == 0) ss[wid][j] = v;
    }
    __syncwarp();

    float sc = (lane < 20) ? ss[wid][lane] : -INFINITY;
    float mx = sc;
#pragma unroll
    for (int off = 16; off; off >>= 1) mx = fmaxf(mx, __shfl_xor_sync(0xffffffffu, mx, off));
    float ex = (lane < 20) ? expf(sc - mx) : 0.f;
    float sm = ex;
#pragma unroll
    for (int off = 16; off; off >>= 1) sm += __shfl_xor_sync(0xffffffffu, sm, off);
    float beta = ex / sm;

    float a0 = 0.f, a1 = 0.f;
    for (int j = 0; j < 20; j++) {
        float bj = __shfl_sync(0xffffffffu, beta, j);
        a0 = fmaf(bj, myf[j * 42 + lane], a0);
        if (lane < 10) a1 = fmaf(bj, myf[j * 42 + 32 + lane], a1);
    }
    float* xr = x + (size_t)n * 128;
    const float* hr = h + (size_t)n * 86;
    for (int i = lane; i < 86; i += 32) xr[i] = hr[i];
    xr[86 + lane] = a0;
    if (lane < 10) xr[118 + lane] = a1;
}

// ---------------- GAT projection GEMM: feat[p] = x @ W[p]  ---------------------
// block: 128x128 output tile, 256 threads, 8x8 microtile, K=128 in 4 slabs of 32
__global__ void k_gemm_feat(const float* __restrict__ x, const float* __restrict__ gatW,
                            float* __restrict__ feat) {
    __shared__ float xs[32][132];  // transposed: xs[k][m]
    __shared__ float ws[32][128];
    int tid = threadIdx.x;
    int tx = tid & 15, ty = tid >> 4;
    int p = blockIdx.y;
    int n0 = blockIdx.x * 128;
    const float* W = gatW + (size_t)p * 128 * 128;
    float acc[8][8];
#pragma unroll
    for (int i = 0; i < 8; i++)
#pragma unroll
        for (int j = 0; j < 8; j++) acc[i][j] = 0.f;

    for (int k0 = 0; k0 < 128; k0 += 32) {
#pragma unroll
        for (int rr = 0; rr < 4; rr++) {
            int m = rr * 32 + (tid >> 3);
            int kk = (tid & 7) * 4;
            int n = n0 + m;
            float4 v = make_float4(0.f, 0.f, 0.f, 0.f);
            if (n < Nn) v = *(const float4*)&x[(size_t)n * 128 + k0 + kk];
            xs[kk + 0][m] = v.x; xs[kk + 1][m] = v.y;
            xs[kk + 2][m] = v.z; xs[kk + 3][m] = v.w;
        }
#pragma unroll
        for (int rr = 0; rr < 4; rr++) {
            int kk = rr * 8 + (tid >> 5);
            int c = (tid & 31) * 4;
            *(float4*)&ws[kk][c] = *(const float4*)&W[(size_t)(k0 + kk) * 128 + c];
        }
        __syncthreads();
#pragma unroll
        for (int k = 0; k < 32; k++) {
            float a[8], b[8];
            *(float4*)&a[0] = *(const float4*)&xs[k][ty * 8];
            *(float4*)&a[4] = *(const float4*)&xs[k][ty * 8 + 4];
            *(float4*)&b[0] = *(const float4*)&ws[k][tx * 8];
            *(float4*)&b[4] = *(const float4*)&ws[k][tx * 8 + 4];
#pragma unroll
            for (int i = 0; i < 8; i++)
#pragma unroll
                for (int j = 0; j < 8; j++) acc[i][j] = fmaf(a[i], b[j], acc[i][j]);
        }
        __syncthreads();
    }
#pragma unroll
    for (int i = 0; i < 8; i++) {
        int n = n0 + ty * 8 + i;
        if (n < Nn) {
            float* o = &feat[((size_t)p * Nn + n) * 128 + tx * 8];
            *(float4*)&o[0] = *(float4*)&acc[i][0];
            *(float4*)&o[4] = *(float4*)&acc[i][4];
        }
    }
}

// ---------------- el/er: warp per (p,n) row -------------------------------------
__global__ void k_eler(const float* __restrict__ feat, const float* __restrict__ al,
                       const float* __restrict__ ar, float* __restrict__ el,
                       float* __restrict__ er) {
    int tid = threadIdx.x, wid = tid >> 5, lane = tid & 31;
    long r = (long)blockIdx.x * 8 + wid;    // r = p*N + n
    if (r >= (long)Pp * Nn) return;
    int p = (int)(r / Nn);
    int hh = lane >> 3;
    int off = (lane & 7) * 4;
    float4 f = *(const float4*)&feat[(size_t)r * 128 + lane * 4];
    float4 a = *(const float4*)&al[((size_t)p * Hh + hh) * 32 + off];
    float4 b = *(const float4*)&ar[((size_t)p * Hh + hh) * 32 + off];
    float vl = f.x * a.x + f.y * a.y + f.z * a.z + f.w * a.w;
    float vr = f.x * b.x + f.y * b.y + f.z * b.z + f.w * b.w;
#pragma unroll
    for (int o = 4; o; o >>= 1) {
        vl += __shfl_down_sync(0xffffffffu, vl, o);
        vr += __shfl_down_sync(0xffffffffu, vr, o);
    }
    if ((lane & 7) == 0) { el[r * 4 + hh] = vl; er[r * 4 + hh] = vr; }
}

// ---------------- edge pass A: e = leaky(el[s]+er[d]); segment max --------------
__global__ void k_edgeA(const int* __restrict__ src, const int* __restrict__ dst,
                        const float* __restrict__ el, const float* __restrict__ er,
                        float* __restrict__ ee, unsigned* __restrict__ mbuf) {
    int p = blockIdx.y;
    int e = blockIdx.x * 256 + threadIdx.x;
    if (e >= Ee) return;
    int s = src[(size_t)p * Ee + e];
    int d = dst[(size_t)p * Ee + e];
    float4 a = *(const float4*)&el[((size_t)p * Nn + s) * 4];
    float4 b = *(const float4*)&er[((size_t)p * Nn + d) * 4];
    float4 v;
    v.x = a.x + b.x; v.x = v.x > 0.f ? v.x : 0.2f * v.x;
    v.y = a.y + b.y; v.y = v.y > 0.f ? v.y : 0.2f * v.y;
    v.z = a.z + b.z; v.z = v.z > 0.f ? v.z : 0.2f * v.z;
    v.w = a.w + b.w; v.w = v.w > 0.f ? v.w : 0.2f * v.w;
    *(float4*)&ee[((size_t)p * Ee + e) * 4] = v;
    unsigned* mp = mbuf + ((size_t)p * Nn + d) * 4;
    atomicMax(mp + 0, encf(v.x));
    atomicMax(mp + 1, encf(v.y));
    atomicMax(mp + 2, encf(v.z));
    atomicMax(mp + 3, encf(v.w));
}

// ---------------- edge pass B: warp/edge; unnormalized softmax aggregation ------
__global__ void k_edgeB(const int* __restrict__ src, const int* __restrict__ dst,
                        const float* __restrict__ ee, const unsigned* __restrict__ mbuf,
                        const float* __restrict__ feat, float* __restrict__ zsum,
                        float* __restrict__ z) {
    int p = blockIdx.y;
    int tid = threadIdx.x, wid = tid >> 5, lane = tid & 31;
    long e = (long)blockIdx.x * 8 + wid;
    if (e >= Ee) return;
    int s = src[(size_t)p * Ee + e];
    int d = dst[(size_t)p * Ee + e];
    float4 ev = *(const float4*)&ee[((size_t)p * Ee + e) * 4];
    uint4 mu = *(const uint4*)&mbuf[((size_t)p * Nn + d) * 4];
    float4 e4;
    e4.x = __expf(ev.x - decf(mu.x));
    e4.y = __expf(ev.y - decf(mu.y));
    e4.z = __expf(ev.z - decf(mu.z));
    e4.w = __expf(ev.w - decf(mu.w));
    int hh = lane >> 3;
    float w = (hh == 0) ? e4.x : (hh == 1) ? e4.y : (hh == 2) ? e4.z : e4.w;
    if ((lane & 7) == 0) atomicAdd(&zsum[((size_t)p * Nn + d) * 4 + hh], w);
    float4 f = *(const float4*)&feat[((size_t)p * Nn + s) * 128 + lane * 4];
    float* zp = &z[((size_t)p * Nn + d) * 128 + lane * 4];
    asm volatile("red.global.add.v4.f32 [%0], {%1,%2,%3,%4};"
                 :: "l"(zp), "f"(w * f.x), "f"(w * f.y), "f"(w * f.z), "f"(w * f.w)
                 : "memory");
}

// ---------------- finalize: z = elu(z / zsum), guard empty nodes ----------------
__global__ void k_final(float* __restrict__ z, const float* __restrict__ zsum) {
    long i = (long)blockIdx.x * 256 + threadIdx.x;  // over P*N*32 float4s
    if (i >= (long)Pp * Nn * 32) return;
    long row = i >> 5;
    int q = (int)(i & 31);
    int hh = q >> 3;
    float zs = zsum[row * 4 + hh];
    float4 v = ((const float4*)z)[i];
    if (zs > 0.f) {
        float inv = 1.f / zs;
        v.x *= inv; v.y *= inv; v.z *= inv; v.w *= inv;
        v.x = v.x > 0.f ? v.x : expm1f(v.x);
        v.y = v.y > 0.f ? v.y : expm1f(v.y);
        v.z = v.z > 0.f ? v.z : expm1f(v.z);
        v.w = v.w > 0.f ? v.w : expm1f(v.w);
    } else {
        v = make_float4(0.f, 0.f, 0.f, 0.f);
    }
    ((float4*)z)[i] = v;
}

// ---------------- semantic attention GEMM + reduce ------------------------------
// wsem[p] += sum_n tanh(z[p,n,:] @ sa_w1 + b1) @ sa_w2
__global__ void k_sem(const float* __restrict__ z, const float* __restrict__ w1,
                      const float* __restrict__ b1, const float* __restrict__ w2,
                      float* __restrict__ wsem) {
    __shared__ float xs[32][132];
    __shared__ float ws[32][128];
    __shared__ float sred[128 * 16];
    __shared__ float sb1[128], sw2[128];
    __shared__ float swred[8];
    int tid = threadIdx.x;
    int tx = tid & 15, ty = tid >> 4;
    int p = blockIdx.y;
    int n0 = blockIdx.x * 128;
    if (tid < 128) { sb1[tid] = b1[tid]; sw2[tid] = w2[tid]; }
    const float* zr = z + (size_t)p * Nn * 128;
    float acc[8][8];
#pragma unroll
    for (int i = 0; i < 8; i++)
#pragma unroll
        for (int j = 0; j < 8; j++) acc[i][j] = 0.f;

    for (int k0 = 0; k0 < 128; k0 += 32) {
#pragma unroll
        for (int rr = 0; rr < 4; rr++) {
            int m = rr * 32 + (tid >> 3);
            int kk = (tid & 7) * 4;
            int n = n0 + m;
            float4 v = make_float4(0.f, 0.f, 0.f, 0.f);
            if (n < Nn) v = *(const float4*)&zr[(size_t)n * 128 + k0 + kk];
            xs[kk + 0][m] = v.x; xs[kk + 1][m] = v.y;
            xs[kk + 2][m] = v.z; xs[kk + 3][m] = v.w;
        }
#pragma unroll
        for (int rr = 0; rr < 4; rr++) {
            int kk = rr * 8 + (tid >> 5);
            int c = (tid & 31) * 4;
            *(float4*)&ws[kk][c] = *(const float4*)&w1[(size_t)(k0 + kk) * 128 + c];
        }
        __syncthreads();
#pragma unroll
        for (int k = 0; k < 32; k++) {
            float a[8], b[8];
            *(float4*)&a[0] = *(const float4*)&xs[k][ty * 8];
            *(float4*)&a[4] = *(const float4*)&xs[k][ty * 8 + 4];
            *(float4*)&b[0] = *(const float4*)&ws[k][tx * 8];
            *(float4*)&b[4] = *(const float4*)&ws[k][tx * 8 + 4];
#pragma unroll
            for (int i = 0; i < 8; i++)
#pragma unroll
                for (int j = 0; j < 8; j++) acc[i][j] = fmaf(a[i], b[j], acc[i][j]);
        }
        __syncthreads();
    }
    // epilogue: tanh + dot with w2, reduce rows
    float rp[8];
#pragma unroll
    for (int i = 0; i < 8; i++) {
        rp[i] = 0.f;
#pragma unroll
        for (int j = 0; j < 8; j++) {
            float t = tanhf(acc[i][j] + sb1[tx * 8 + j]);
            rp[i] = fmaf(t, sw2[tx * 8 + j], rp[i]);
        }
    }
#pragma unroll
    for (int i = 0; i < 8; i++) sred[(ty * 8 + i) * 16 + tx] = rp[i];
    __syncthreads();
    float v = 0.f;
    if (tid < 128 && (n0 + tid) < Nn) {
#pragma unroll
        for (int t = 0; t < 16; t++) v += sred[tid * 16 + t];
    }
#pragma unroll
    for (int off = 16; off; off >>= 1) v += __shfl_xor_sync(0xffffffffu, v, off);
    if ((tid & 31) == 0) swred[tid >> 5] = v;
    __syncthreads();
    if (tid == 0) {
        float s = 0.f;
#pragma unroll
        for (int i = 0; i < 8; i++) s += swred[i];
        atomicAdd(&wsem[p], s);
    }
}

// ---------------- softmax over 3 meta-paths -------------------------------------
__global__ void k_bsem(const float* __restrict__ wsem, float* __restrict__ bsem) {
    float w0 = wsem[0] / (float)Nn, w1 = wsem[1] / (float)Nn, w2 = wsem[2] / (float)Nn;
    float m = fmaxf(w0, fmaxf(w1, w2));
    float e0 = expf(w0 - m), e1 = expf(w1 - m), e2 = expf(w2 - m);
    float s = e0 + e1 + e2;
    bsem[0] = e0 / s; bsem[1] = e1 / s; bsem[2] = e2 / s;
}

// ---------------- combine: out = sum_p bsem[p] * z[p] ---------------------------
__global__ void k_comb(const float* __restrict__ z, const float* __restrict__ bsem,
                       float* __restrict__ out) {
    long i = (long)blockIdx.x * 256 + threadIdx.x;  // over N*32 float4s
    if (i >= (long)Nn * 32) return;
    float b0 = bsem[0], b1 = bsem[1], b2 = bsem[2];
    const float4* z4 = (const float4*)z;
    float4 v0 = z4[i];
    float4 v1 = z4[(size_t)Nn * 32 + i];
    float4 v2 = z4[2 * (size_t)Nn * 32 + i];
    float4 o;
    o.x = b0 * v0.x + b1 * v1.x + b2 * v2.x;
    o.y = b0 * v0.y + b1 * v1.y + b2 * v2.y;
    o.z = b0 * v0.z + b1 * v1.z + b2 * v2.z;
    o.w = b0 * v0.w + b1 * v1.w + b2 * v2.w;
    ((float4*)out)[i] = o;
}

// ---------------- launch ---------------------------------------------------------
extern "C" void kernel_launch(void* const* d_in, const int* in_sizes, int n_in,
                              void* d_out, int out_size) {
    const float* h      = (const float*)d_in[0];
    const float* cf     = (const float*)d_in[1];
    const float* fa_w1  = (const float*)d_in[2];
    const float* fa_b1  = (const float*)d_in[3];
    const float* fa_w2  = (const float*)d_in[4];
    const float* gat_W  = (const float*)d_in[5];
    const float* attn_l = (const float*)d_in[6];
    const float* attn_r = (const float*)d_in[7];
    const float* sa_w1  = (const float*)d_in[8];
    const float* sa_b1  = (const float*)d_in[9];
    const float* sa_w2  = (const float*)d_in[10];
    const int*   src    = (const int*)d_in[11];
    const int*   dst    = (const int*)d_in[12];
    float* out = (float*)d_out;

    float *px, *pfeat, *pz, *pel, *per, *pee, *pzsum, *pwsem, *pbsem;
    unsigned* pm;
    cudaGetSymbolAddress((void**)&px, g_x);
    cudaGetSymbolAddress((void**)&pfeat, g_feat);
    cudaGetSymbolAddress((void**)&pz, g_z);
    cudaGetSymbolAddress((void**)&pel, g_el);
    cudaGetSymbolAddress((void**)&per, g_er);
    cudaGetSymbolAddress((void**)&pee, g_ee);
    cudaGetSymbolAddress((void**)&pm, g_m);
    cudaGetSymbolAddress((void**)&pzsum, g_zsum);
    cudaGetSymbolAddress((void**)&pwsem, g_wsem);
    cudaGetSymbolAddress((void**)&pbsem, g_bsem);

    // zero aggregation buffer + init encoded maxima / sums
    cudaMemsetAsync(pz, 0, sizeof(float) * (size_t)Pp * Nn * 128, 0);
    k_init<<<(Pp * Nn * 4 + 255) / 256, 256>>>(pm, pzsum, pwsem);

    // 1) feature attention -> x
    k_featatt<<<(Nn + 7) / 8, 256>>>(h, cf, fa_w1, fa_b1, fa_w2, px);

    // 2) per-path projection GEMMs -> feat
    dim3 gg((Nn + 127) / 128, Pp);
    k_gemm_feat<<<gg, 256>>>(px, gat_W, pfeat);

    // 3) attention logits per node
    k_eler<<<(Pp * Nn + 7) / 8, 256>>>(pfeat, attn_l, attn_r, pel, per);

    // 4) edge passes
    dim3 ga((Ee + 255) / 256, Pp);
    k_edgeA<<<ga, 256>>>(src, dst, pel, per, pee, pm);
    dim3 gb((Ee + 7) / 8, Pp);
    k_edgeB<<<gb, 256>>>(src, dst, pee, pm, pfeat, pzsum, pz);

    // 5) normalize + elu
    long tot4 = (long)Pp * Nn * 32;
    k_final<<<(unsigned)((tot4 + 255) / 256), 256>>>(pz, pzsum);

    // 6) semantic attention
    k_sem<<<gg, 256>>>(pz, sa_w1, sa_b1, sa_w2, pwsem);
    k_bsem<<<1, 1>>>(pwsem, pbsem);

    // 7) combine
    k_comb<<<(unsigned)(((long)Nn * 32 + 255) / 256), 256>>>(pz, pbsem, out);
}

// round 2
// speedup vs baseline: 1.1316x; 1.1316x over previous
#include <cuda_runtime.h>
#include <math.h>
#include <stdint.h>

#define Nn 50000
#define Ee 400000
#define Pp 3
#define Hh 4
#define Dd 32
#define HDd 128

// ---------------- scratch (device globals) --------------------------------------
__device__ __align__(16) float g_x[(size_t)Nn * 128];            // 25.6 MB
__device__ __align__(16) float g_feat[(size_t)Pp * Nn * 128];    // 76.8 MB
__device__ __align__(16) float g_z[(size_t)Pp * Nn * 128];       // 76.8 MB
__device__ __align__(16) float g_el[(size_t)Pp * Nn * 4];
__device__ __align__(16) float g_er[(size_t)Pp * Nn * 4];
__device__ __align__(16) float g_ee[(size_t)Pp * Ee * 4];        // 19.2 MB
__device__ int g_deg[(size_t)Pp * Nn];
__device__ int g_off[(size_t)Pp * (Nn + 1)];
__device__ int g_cur[(size_t)Pp * Nn];
__device__ int g_eid[(size_t)Pp * Ee];
__device__ float g_wsem[Pp];
__device__ float g_bsem[Pp];

// ---------------- feature attention: warp per node -----------------------------
__global__ void k_featatt(const float* __restrict__ h, const float* __restrict__ cf,
                          const float* __restrict__ w1, const float* __restrict__ b1,
                          const float* __restrict__ w2, float* __restrict__ x) {
    __shared__ float sw1[42 * 16];
    __shared__ float sb1[16], sw2[16];
    __shared__ float sf[8][840];
    __shared__ float ss[8][20];
    int tid = threadIdx.x, wid = tid >> 5, lane = tid & 31;
    for (int i = tid; i < 672; i += 256) sw1[i] = w1[i];
    if (tid < 16) { sb1[tid] = b1[tid]; sw2[tid] = w2[tid]; }
    __syncthreads();
    int n = blockIdx.x * 8 + wid;
    if (n >= Nn) return;

    const float* fr = cf + (size_t)n * 840;
    float* myf = sf[wid];
    for (int i = lane; i < 840; i += 32) myf[i] = fr[i];
    __syncwarp();

    int k = lane & 15;
    for (int j0 = 0; j0 < 20; j0 += 2) {
        int j = j0 + (lane >> 4);
        const float* fj = myf + j * 42;
        float acc = sb1[k];
#pragma unroll
        for (int i = 0; i < 42; i++) acc = fmaf(fj[i], sw1[i * 16 + k], acc);
        float v = tanhf(acc) * sw2[k];
#pragma unroll
        for (int off = 8; off; off >>= 1) v += __shfl_down_sync(0xffffffffu, v, off);
        if (k == 0) ss[wid][j] = v;
    }
    __syncwarp();

    float sc = (lane < 20) ? ss[wid][lane] : -INFINITY;
    float mx = sc;
#pragma unroll
    for (int off = 16; off; off >>= 1) mx = fmaxf(mx, __shfl_xor_sync(0xffffffffu, mx, off));
    float ex = (lane < 20) ? expf(sc - mx) : 0.f;
    float sm = ex;
#pragma unroll
    for (int off = 16; off; off >>= 1) sm += __shfl_xor_sync(0xffffffffu, sm, off);
    float beta = ex / sm;

    float a0 = 0.f, a1 = 0.f;
    for (int j = 0; j < 20; j++) {
        float bj = __shfl_sync(0xffffffffu, beta, j);
        a0 = fmaf(bj, myf[j * 42 + lane], a0);
        if (lane < 10) a1 = fmaf(bj, myf[j * 42 + 32 + lane], a1);
    }
    float* xr = x + (size_t)n * 128;
    const float* hr = h + (size_t)n * 86;
    for (int i = lane; i < 86; i += 32) xr[i] = hr[i];
    xr[86 + lane] = a0;
    if (lane < 10) xr[118 + lane] = a1;
}

// ---------------- GAT projection GEMM + fused el/er epilogue --------------------
__global__ void k_gemm_feat(const float* __restrict__ x, const float* __restrict__ gatW,
                            const float* __restrict__ al, const float* __restrict__ ar,
                            float* __restrict__ feat, float* __restrict__ el,
                            float* __restrict__ er) {
    __shared__ float xs[32][132];   // reused as s_el in epilogue
    __shared__ float ws[32][128];   // reused as s_er in epilogue
    __shared__ float sal[128], sar[128];
    int tid = threadIdx.x;
    int tx = tid & 15, ty = tid >> 4;
    int p = blockIdx.y;
    int n0 = blockIdx.x * 128;
    const float* W = gatW + (size_t)p * 128 * 128;
    if (tid < 128) { sal[tid] = al[p * 128 + tid]; sar[tid] = ar[p * 128 + tid]; }
    float acc[8][8];
#pragma unroll
    for (int i = 0; i < 8; i++)
#pragma unroll
        for (int j = 0; j < 8; j++) acc[i][j] = 0.f;

    for (int k0 = 0; k0 < 128; k0 += 32) {
#pragma unroll
        for (int rr = 0; rr < 4; rr++) {
            int m = rr * 32 + (tid >> 3);
            int kk = (tid & 7) * 4;
            int n = n0 + m;
            float4 v = make_float4(0.f, 0.f, 0.f, 0.f);
            if (n < Nn) v = *(const float4*)&x[(size_t)n * 128 + k0 + kk];
            xs[kk + 0][m] = v.x; xs[kk + 1][m] = v.y;
            xs[kk + 2][m] = v.z; xs[kk + 3][m] = v.w;
        }
#pragma unroll
        for (int rr = 0; rr < 4; rr++) {
            int kk = rr * 8 + (tid >> 5);
            int c = (tid & 31) * 4;
            *(float4*)&ws[kk][c] = *(const float4*)&W[(size_t)(k0 + kk) * 128 + c];
        }
        __syncthreads();
#pragma unroll
        for (int k = 0; k < 32; k++) {
            float a[8], b[8];
            *(float4*)&a[0] = *(const float4*)&xs[k][ty * 8];
            *(float4*)&a[4] = *(const float4*)&xs[k][ty * 8 + 4];
            *(float4*)&b[0] = *(const float4*)&ws[k][tx * 8];
            *(float4*)&b[4] = *(const float4*)&ws[k][tx * 8 + 4];
#pragma unroll
            for (int i = 0; i < 8; i++)
#pragma unroll
                for (int j = 0; j < 8; j++) acc[i][j] = fmaf(a[i], b[j], acc[i][j]);
        }
        __syncthreads();
    }
    // store feat tile
#pragma unroll
    for (int i = 0; i < 8; i++) {
        int n = n0 + ty * 8 + i;
        if (n < Nn) {
            float* o = &feat[((size_t)p * Nn + n) * 128 + tx * 8];
            *(float4*)&o[0] = *(float4*)&acc[i][0];
            *(float4*)&o[4] = *(float4*)&acc[i][4];
        }
    }
    // fused el/er: partial dots per thread -> smem -> per-row reduce
    float* s_el = &xs[0][0];   // 128*16 floats
    float* s_er = &ws[0][0];
#pragma unroll
    for (int i = 0; i < 8; i++) {
        float pl = 0.f, pr = 0.f;
#pragma unroll
        for (int j = 0; j < 8; j++) {
            pl = fmaf(acc[i][j], sal[tx * 8 + j], pl);
            pr = fmaf(acc[i][j], sar[tx * 8 + j], pr);
        }
        s_el[(ty * 8 + i) * 16 + tx] = pl;
        s_er[(ty * 8 + i) * 16 + tx] = pr;
    }
    __syncthreads();
    if (tid < 128) {
        int n = n0 + tid;
        if (n < Nn) {
            long r = (long)p * Nn + n;
            float4 e4, f4;
            float* pe = &e4.x;
            float* pf = &f4.x;
#pragma unroll
            for (int hh = 0; hh < 4; hh++) {
                float sl = 0.f, sr = 0.f;
#pragma unroll
                for (int t = 0; t < 4; t++) {
                    sl += s_el[tid * 16 + hh * 4 + t];
                    sr += s_er[tid * 16 + hh * 4 + t];
                }
                pe[hh] = sl; pf[hh] = sr;
            }
            *(float4*)&el[r * 4] = e4;
            *(float4*)&er[r * 4] = f4;
        }
    }
}

// ---------------- CSR build: count, scan, scatter --------------------------------
__global__ void k_count(const int* __restrict__ dst, int* __restrict__ deg) {
    int p = blockIdx.y;
    int e = blockIdx.x * 256 + threadIdx.x;
    if (e >= Ee) return;
    atomicAdd(&deg[(size_t)p * Nn + dst[(size_t)p * Ee + e]], 1);
}

__global__ void k_scan(const int* __restrict__ deg, int* __restrict__ off,
                       int* __restrict__ cur) {
    int p = blockIdx.x;
    int tid = threadIdx.x, lane = tid & 31, wid = tid >> 5;
    __shared__ int wsum[32];
    __shared__ int carry;
    if (tid == 0) carry = 0;
    __syncthreads();
    for (int base = 0; base < Nn; base += 1024) {
        int i = base + tid;
        int v = (i < Nn) ? deg[(size_t)p * Nn + i] : 0;
        int xv = v;
#pragma unroll
        for (int o = 1; o < 32; o <<= 1) {
            int t = __shfl_up_sync(0xffffffffu, xv, o);
            if (lane >= o) xv += t;
        }
        if (lane == 31) wsum[wid] = xv;
        __syncthreads();
        if (wid == 0) {
            int y = wsum[lane];
#pragma unroll
            for (int o = 1; o < 32; o <<= 1) {
                int t = __shfl_up_sync(0xffffffffu, y, o);
                if (lane >= o) y += t;
            }
            wsum[lane] = y;
        }
        __syncthreads();
        int wpre = (wid == 0) ? 0 : wsum[wid - 1];
        int excl = carry + wpre + xv - v;
        if (i < Nn) {
            off[(size_t)p * (Nn + 1) + i] = excl;
            cur[(size_t)p * Nn + i] = excl;
        }
        __syncthreads();
        if (tid == 1023) carry = excl + v;
        __syncthreads();
    }
    if (tid == 0) off[(size_t)p * (Nn + 1) + Nn] = carry;
}

__global__ void k_scatter(const int* __restrict__ dst, int* __restrict__ cur,
                          int* __restrict__ eid) {
    int p = blockIdx.y;
    int e = blockIdx.x * 256 + threadIdx.x;
    if (e >= Ee) return;
    int d = dst[(size_t)p * Ee + e];
    int pos = atomicAdd(&cur[(size_t)p * Nn + d], 1);
    eid[(size_t)p * Ee + pos] = e;
}

// ---------------- edge logits: e = leaky(el[s]+er[d]) ----------------------------
__global__ void k_edgeA(const int* __restrict__ src, const int* __restrict__ dst,
                        const float* __restrict__ el, const float* __restrict__ er,
                        float* __restrict__ ee) {
    int p = blockIdx.y;
    int e = blockIdx.x * 256 + threadIdx.x;
    if (e >= Ee) return;
    int s = src[(size_t)p * Ee + e];
    int d = dst[(size_t)p * Ee + e];
    float4 a = *(const float4*)&el[((size_t)p * Nn + s) * 4];
    float4 b = *(const float4*)&er[((size_t)p * Nn + d) * 4];
    float4 v;
    v.x = a.x + b.x; v.x = v.x > 0.f ? v.x : 0.2f * v.x;
    v.y = a.y + b.y; v.y = v.y > 0.f ? v.y : 0.2f * v.y;
    v.z = a.z + b.z; v.z = v.z > 0.f ? v.z : 0.2f * v.z;
    v.w = a.w + b.w; v.w = v.w > 0.f ? v.w : 0.2f * v.w;
    *(float4*)&ee[((size_t)p * Ee + e) * 4] = v;
}

// ---------------- gather aggregation: warp per (p, dst) --------------------------
__global__ void k_gather(const int* __restrict__ src, const int* __restrict__ off,
                         const int* __restrict__ eid, const float* __restrict__ ee,
                         const float* __restrict__ feat, float* __restrict__ z) {
    int p = blockIdx.y;
    int tid = threadIdx.x, wid = tid >> 5, lane = tid & 31;
    int n = blockIdx.x * 8 + wid;
    if (n >= Nn) return;
    long r = (long)p * Nn + n;
    int start = off[(size_t)p * (Nn + 1) + n];
    int end = off[(size_t)p * (Nn + 1) + n + 1];
    float* zp = &z[r * 128 + lane * 4];
    if (start == end) {
        *(float4*)zp = make_float4(0.f, 0.f, 0.f, 0.f);
        return;
    }
    const int* eidp = eid + (size_t)p * Ee;
    const int* srcp = src + (size_t)p * Ee;
    const float4* eep = (const float4*)(ee) + (size_t)p * Ee;

    // pass 1: segment max per head
    float4 mx = make_float4(-INFINITY, -INFINITY, -INFINITY, -INFINITY);
    for (int i = start + lane; i < end; i += 32) {
        float4 v = eep[eidp[i]];
        mx.x = fmaxf(mx.x, v.x); mx.y = fmaxf(mx.y, v.y);
        mx.z = fmaxf(mx.z, v.z); mx.w = fmaxf(mx.w, v.w);
    }
#pragma unroll
    for (int o = 16; o; o >>= 1) {
        mx.x = fmaxf(mx.x, __shfl_xor_sync(0xffffffffu, mx.x, o));
        mx.y = fmaxf(mx.y, __shfl_xor_sync(0xffffffffu, mx.y, o));
        mx.z = fmaxf(mx.z, __shfl_xor_sync(0xffffffffu, mx.z, o));
        mx.w = fmaxf(mx.w, __shfl_xor_sync(0xffffffffu, mx.w, o));
    }

    // pass 2: weighted accumulation (edge-serial, warp-wide feature parallel)
    int head = lane >> 3;
    float4 acc = make_float4(0.f, 0.f, 0.f, 0.f);
    float4 zs = make_float4(0.f, 0.f, 0.f, 0.f);
    int i = start;
    for (; i + 1 < end; i += 2) {
        int e0 = eidp[i], e1 = eidp[i + 1];
        int s0 = srcp[e0], s1 = srcp[e1];
        float4 v0 = eep[e0], v1 = eep[e1];
        float4 f0 = *(const float4*)&feat[((size_t)p * Nn + s0) * 128 + lane * 4];
        float4 f1 = *(const float4*)&feat[((size_t)p * Nn + s1) * 128 + lane * 4];
        float4 w0, w1;
        w0.x = __expf(v0.x - mx.x); w0.y = __expf(v0.y - mx.y);
        w0.z = __expf(v0.z - mx.z); w0.w = __expf(v0.w - mx.w);
        w1.x = __expf(v1.x - mx.x); w1.y = __expf(v1.y - mx.y);
        w1.z = __expf(v1.z - mx.z); w1.w = __expf(v1.w - mx.w);
        zs.x += w0.x + w1.x; zs.y += w0.y + w1.y;
        zs.z += w0.z + w1.z; zs.w += w0.w + w1.w;
        float a0 = head == 0 ? w0.x : head == 1 ? w0.y : head == 2 ? w0.z : w0.w;
        float a1 = head == 0 ? w1.x : head == 1 ? w1.y : head == 2 ? w1.z : w1.w;
        acc.x = fmaf(a0, f0.x, acc.x); acc.x = fmaf(a1, f1.x, acc.x);
        acc.y = fmaf(a0, f0.y, acc.y); acc.y = fmaf(a1, f1.y, acc.y);
        acc.z = fmaf(a0, f0.z, acc.z); acc.z = fmaf(a1, f1.z, acc.z);
        acc.w = fmaf(a0, f0.w, acc.w); acc.w = fmaf(a1, f1.w, acc.w);
    }
    if (i < end) {
        int e0 = eidp[i];
        int s0 = srcp[e0];
        float4 v0 = eep[e0];
        float4 f0 = *(const float4*)&feat[((size_t)p * Nn + s0) * 128 + lane * 4];
        float4 w0;
        w0.x = __expf(v0.x - mx.x); w0.y = __expf(v0.y - mx.y);
        w0.z = __expf(v0.z - mx.z); w0.w = __expf(v0.w - mx.w);
        zs.x += w0.x; zs.y += w0.y; zs.z += w0.z; zs.w += w0.w;
        float a0 = head == 0 ? w0.x : head == 1 ? w0.y : head == 2 ? w0.z : w0.w;
        acc.x = fmaf(a0, f0.x, acc.x);
        acc.y = fmaf(a0, f0.y, acc.y);
        acc.z = fmaf(a0, f0.z, acc.z);
        acc.w = fmaf(a0, f0.w, acc.w);
    }
    float zsel = head == 0 ? zs.x : head == 1 ? zs.y : head == 2 ? zs.z : zs.w;
    float inv = 1.f / zsel;
    acc.x *= inv; acc.y *= inv; acc.z *= inv; acc.w *= inv;
    acc.x = acc.x > 0.f ? acc.x : expm1f(acc.x);
    acc.y = acc.y > 0.f ? acc.y : expm1f(acc.y);
    acc.z = acc.z > 0.f ? acc.z : expm1f(acc.z);
    acc.w = acc.w > 0.f ? acc.w : expm1f(acc.w);
    *(float4*)zp = acc;
}

// ---------------- semantic attention GEMM + reduce ------------------------------
__global__ void k_sem(const float* __restrict__ z, const float* __restrict__ w1,
                      const float* __restrict__ b1, const float* __restrict__ w2,
                      float* __restrict__ wsem) {
    __shared__ float xs[32][132];
    __shared__ float ws[32][128];
    __shared__ float sred[128 * 16];
    __shared__ float sb1[128], sw2[128];
    __shared__ float swred[8];
    int tid = threadIdx.x;
    int tx = tid & 15, ty = tid >> 4;
    int p = blockIdx.y;
    int n0 = blockIdx.x * 128;
    if (tid < 128) { sb1[tid] = b1[tid]; sw2[tid] = w2[tid]; }
    const float* zr = z + (size_t)p * Nn * 128;
    float acc[8][8];
#pragma unroll
    for (int i = 0; i < 8; i++)
#pragma unroll
        for (int j = 0; j < 8; j++) acc[i][j] = 0.f;

    for (int k0 = 0; k0 < 128; k0 += 32) {
#pragma unroll
        for (int rr = 0; rr < 4; rr++) {
            int m = rr * 32 + (tid >> 3);
            int kk = (tid & 7) * 4;
            int n = n0 + m;
            float4 v = make_float4(0.f, 0.f, 0.f, 0.f);
            if (n < Nn) v = *(const float4*)&zr[(size_t)n * 128 + k0 + kk];
            xs[kk + 0][m] = v.x; xs[kk + 1][m] = v.y;
            xs[kk + 2][m] = v.z; xs[kk + 3][m] = v.w;
        }
#pragma unroll
        for (int rr = 0; rr < 4; rr++) {
            int kk = rr * 8 + (tid >> 5);
            int c = (tid & 31) * 4;
            *(float4*)&ws[kk][c] = *(const float4*)&w1[(size_t)(k0 + kk) * 128 + c];
        }
        __syncthreads();
#pragma unroll
        for (int k = 0; k < 32; k++) {
            float a[8], b[8];
            *(float4*)&a[0] = *(const float4*)&xs[k][ty * 8];
            *(float4*)&a[4] = *(const float4*)&xs[k][ty * 8 + 4];
            *(float4*)&b[0] = *(const float4*)&ws[k][tx * 8];
            *(float4*)&b[4] = *(const float4*)&ws[k][tx * 8 + 4];
#pragma unroll
            for (int i = 0; i < 8; i++)
#pragma unroll
                for (int j = 0; j < 8; j++) acc[i][j] = fmaf(a[i], b[j], acc[i][j]);
        }
        __syncthreads();
    }
    float rp[8];
#pragma unroll
    for (int i = 0; i < 8; i++) {
        rp[i] = 0.f;
#pragma unroll
        for (int j = 0; j < 8; j++) {
            float t = tanhf(acc[i][j] + sb1[tx * 8 + j]);
            rp[i] = fmaf(t, sw2[tx * 8 + j], rp[i]);
        }
    }
#pragma unroll
    for (int i = 0; i < 8; i++) sred[(ty * 8 + i) * 16 + tx] = rp[i];
    __syncthreads();
    float v = 0.f;
    if (tid < 128 && (n0 + tid) < Nn) {
#pragma unroll
        for (int t = 0; t < 16; t++) v += sred[tid * 16 + t];
    }
#pragma unroll
    for (int off = 16; off; off >>= 1) v += __shfl_xor_sync(0xffffffffu, v, off);
    if ((tid & 31) == 0) swred[tid >> 5] = v;
    __syncthreads();
    if (tid == 0) {
        float s = 0.f;
#pragma unroll
        for (int i = 0; i < 8; i++) s += swred[i];
        atomicAdd(&wsem[p], s);
    }
}

__global__ void k_bsem(const float* __restrict__ wsem, float* __restrict__ bsem) {
    float w0 = wsem[0] / (float)Nn, w1 = wsem[1] / (float)Nn, w2 = wsem[2] / (float)Nn;
    float m = fmaxf(w0, fmaxf(w1, w2));
    float e0 = expf(w0 - m), e1 = expf(w1 - m), e2 = expf(w2 - m);
    float s = e0 + e1 + e2;
    bsem[0] = e0 / s; bsem[1] = e1 / s; bsem[2] = e2 / s;
}

__global__ void k_comb(const float* __restrict__ z, const float* __restrict__ bsem,
                       float* __restrict__ out) {
    long i = (long)blockIdx.x * 256 + threadIdx.x;
    if (i >= (long)Nn * 32) return;
    float b0 = bsem[0], b1 = bsem[1], b2 = bsem[2];
    const float4* z4 = (const float4*)z;
    float4 v0 = z4[i];
    float4 v1 = z4[(size_t)Nn * 32 + i];
    float4 v2 = z4[2 * (size_t)Nn * 32 + i];
    float4 o;
    o.x = b0 * v0.x + b1 * v1.x + b2 * v2.x;
    o.y = b0 * v0.y + b1 * v1.y + b2 * v2.y;
    o.z = b0 * v0.z + b1 * v1.z + b2 * v2.z;
    o.w = b0 * v0.w + b1 * v1.w + b2 * v2.w;
    ((float4*)out)[i] = o;
}

// ---------------- launch ----------------------------------------------------------
extern "C" void kernel_launch(void* const* d_in, const int* in_sizes, int n_in,
                              void* d_out, int out_size) {
    const float* h      = (const float*)d_in[0];
    const float* cf     = (const float*)d_in[1];
    const float* fa_w1  = (const float*)d_in[2];
    const float* fa_b1  = (const float*)d_in[3];
    const float* fa_w2  = (const float*)d_in[4];
    const float* gat_W  = (const float*)d_in[5];
    const float* attn_l = (const float*)d_in[6];
    const float* attn_r = (const float*)d_in[7];
    const float* sa_w1  = (const float*)d_in[8];
    const float* sa_b1  = (const float*)d_in[9];
    const float* sa_w2  = (const float*)d_in[10];
    const int*   src    = (const int*)d_in[11];
    const int*   dst    = (const int*)d_in[12];
    float* out = (float*)d_out;

    float *px, *pfeat, *pz, *pel, *per, *pee, *pwsem, *pbsem;
    int *pdeg, *poff, *pcur, *peid;
    cudaGetSymbolAddress((void**)&px, g_x);
    cudaGetSymbolAddress((void**)&pfeat, g_feat);
    cudaGetSymbolAddress((void**)&pz, g_z);
    cudaGetSymbolAddress((void**)&pel, g_el);
    cudaGetSymbolAddress((void**)&per, g_er);
    cudaGetSymbolAddress((void**)&pee, g_ee);
    cudaGetSymbolAddress((void**)&pdeg, g_deg);
    cudaGetSymbolAddress((void**)&poff, g_off);
    cudaGetSymbolAddress((void**)&pcur, g_cur);
    cudaGetSymbolAddress((void**)&peid, g_eid);
    cudaGetSymbolAddress((void**)&pwsem, g_wsem);
    cudaGetSymbolAddress((void**)&pbsem, g_bsem);

    cudaMemsetAsync(pdeg, 0, sizeof(int) * (size_t)Pp * Nn, 0);
    cudaMemsetAsync(pwsem, 0, sizeof(float) * Pp, 0);

    // 1) feature attention -> x
    k_featatt<<<(Nn + 7) / 8, 256>>>(h, cf, fa_w1, fa_b1, fa_w2, px);

    // 2) CSR build (independent of x)
    dim3 ge((Ee + 255) / 256, Pp);
    k_count<<<ge, 256>>>(dst, pdeg);
    k_scan<<<Pp, 1024>>>(pdeg, poff, pcur);
    k_scatter<<<ge, 256>>>(dst, pcur, peid);

    // 3) projection GEMM + fused el/er
    dim3 gg((Nn + 127) / 128, Pp);
    k_gemm_feat<<<gg, 256>>>(px, gat_W, attn_l, attn_r, pfeat, pel, per);

    // 4) edge logits
    k_edgeA<<<ge, 256>>>(src, dst, pel, per, pee);

    // 5) gather aggregation (softmax + message sum + elu), one z write
    dim3 gn((Nn + 7) / 8, Pp);
    k_gather<<<gn, 256>>>(src, poff, peid, pee, pfeat, pz);

    // 6) semantic attention
    k_sem<<<gg, 256>>>(pz, sa_w1, sa_b1, sa_w2, pwsem);
    k_bsem<<<1, 1>>>(pwsem, pbsem);

    // 7) combine
    k_comb<<<(unsigned)(((long)Nn * 32 + 255) / 256), 256>>>(pz, pbsem, out);
}